// round 2
// baseline (speedup 1.0000x reference)
#include <cuda_runtime.h>
#include <cuda_bf16.h>

// Problem constants (shapes fixed by the reference)
constexpr int NCH   = 32;     // n channels
constexpr int KNB   = 32;     // K neighbours
constexpr int MCL   = 16;     // M clusters
constexpr float MU_C = 1.0f;
constexpr int NMAX  = 131072; // scratch upper bound for N
constexpr int PB_BLOCKS = 148;

// ---- device scratch (no allocations allowed) ----
static __device__ float g_encpart[16 * NCH];            // per-chunk partial dots for encoded
static __device__ float g_encoded[NCH];                 // encoded vector
static __device__ float g_a[MCL * NCH];                 // a[m][i] = 1/(bw[i,m]*MU)^2
static __device__ float g_dect[(size_t)NMAX * NCH];     // dec_t[p][i] = decoder[i][p]*encoded[i]
static __device__ float g_Spart[PB_BLOCKS * NCH * KNB]; // per-block partial S, layout [block][k][i]
static __device__ float g_invS[KNB * NCH];              // invS[k][i]

// ------------------------------------------------------------------
// Kernel A: partial dot products for encoded[i] = enc_w[i,:] . x
// grid = (16 chunks, 32 rows), 256 threads
// ------------------------------------------------------------------
__global__ void kA_encoded(const float* __restrict__ enc_w,
                           const float* __restrict__ x, int N) {
    int c = blockIdx.x;   // chunk
    int r = blockIdx.y;   // row (channel)
    int chunk = (N + 15) / 16;
    int p0 = c * chunk;
    int p1 = min(p0 + chunk, N);

    const float* __restrict__ row = enc_w + (size_t)r * N;
    float s = 0.0f;
    for (int p = p0 + threadIdx.x; p < p1; p += blockDim.x)
        s += row[p] * x[p];

    // warp reduce
    #pragma unroll
    for (int o = 16; o > 0; o >>= 1)
        s += __shfl_xor_sync(0xffffffffu, s, o);

    __shared__ float ws[8];
    int lane = threadIdx.x & 31, wid = threadIdx.x >> 5;
    if (lane == 0) ws[wid] = s;
    __syncthreads();
    if (threadIdx.x == 0) {
        float t = 0.0f;
        #pragma unroll
        for (int w = 0; w < 8; w++) t += ws[w];
        g_encpart[c * NCH + r] = t;
    }
}

// ------------------------------------------------------------------
// Kernel B: reduce encoded partials, compute bandwidths -> a[m][i]
// 1 block, 512 threads
// ------------------------------------------------------------------
__global__ void kB_bandwidths(const float* __restrict__ bw_w,
                              const float* __restrict__ bw_b,
                              const float* __restrict__ enc_b) {
    __shared__ float enc_s[NCH];
    int t = threadIdx.x;
    if (t < NCH) {
        float s = enc_b[t];
        #pragma unroll
        for (int c = 0; c < 16; c++) s += g_encpart[c * NCH + t];
        enc_s[t] = s;
        g_encoded[t] = s;
    }
    __syncthreads();

    // t indexes the (n*M) bandwidth rows: t = i*M + m
    float s = bw_b[t];
    const float* __restrict__ wrow = bw_w + (size_t)t * NCH;
    #pragma unroll
    for (int q = 0; q < NCH; q++) s += wrow[q] * enc_s[q];
    float w = s * MU_C;
    int i = t / MCL, m = t % MCL;
    g_a[m * NCH + i] = 1.0f / (w * w);
}

// ------------------------------------------------------------------
// Kernel T: transposed + encoded-folded decoder
// dec_t[p][i] = decoder[i][p] * encoded[i]
// ------------------------------------------------------------------
__global__ void kT_transpose(const float* __restrict__ decoder, int N) {
    __shared__ float enc_s[NCH];
    if (threadIdx.x < NCH) enc_s[threadIdx.x] = g_encoded[threadIdx.x];
    __syncthreads();

    int p = blockIdx.x * blockDim.x + threadIdx.x;
    if (p >= N) return;

    float v[NCH];
    #pragma unroll
    for (int i = 0; i < NCH; i++)
        v[i] = decoder[(size_t)i * N + p] * enc_s[i];

    float4* dst = reinterpret_cast<float4*>(g_dect + (size_t)p * NCH);
    #pragma unroll
    for (int q = 0; q < NCH / 4; q++)
        dst[q] = make_float4(v[4*q], v[4*q+1], v[4*q+2], v[4*q+3]);
}

// ------------------------------------------------------------------
// Kernel PB: S[i,k] = sum_j relu(1 - d[j,k]^2 * a[i, lab_j])
// warp-per-j (grid-stride), lane = i. 148 blocks x 512 threads.
// Block partial -> g_Spart[block][k][i]
// ------------------------------------------------------------------
__global__ void __launch_bounds__(512) kPB_sums(
        const float* __restrict__ nd, const int* __restrict__ labels, int N) {
    __shared__ float a_s[MCL * NCH];
    __shared__ float S_sm[KNB * NCH];
    int t = threadIdx.x;
    if (t < MCL * NCH) a_s[t] = g_a[t];
    for (int u = t; u < KNB * NCH; u += 512) S_sm[u] = 0.0f;
    __syncthreads();

    int lane = t & 31, wid = t >> 5;       // 16 warps
    int gw = blockIdx.x * 16 + wid;
    int nw = gridDim.x * 16;

    float acc[KNB];
    #pragma unroll
    for (int k = 0; k < KNB; k++) acc[k] = 0.0f;

    for (int j = gw; j < N; j += nw) {
        float dd = nd[(size_t)j * KNB + lane];
        float d2l = dd * dd;
        int lab = labels[j];
        float a = a_s[lab * NCH + lane];
        #pragma unroll
        for (int k = 0; k < KNB; k++) {
            float d2 = __shfl_sync(0xffffffffu, d2l, k);
            acc[k] += fmaxf(fmaf(-d2, a, 1.0f), 0.0f);
        }
    }

    #pragma unroll
    for (int k = 0; k < KNB; k++)
        atomicAdd(&S_sm[k * NCH + lane], acc[k]);
    __syncthreads();

    for (int u = t; u < KNB * NCH; u += 512)
        g_Spart[blockIdx.x * (KNB * NCH) + u] = S_sm[u];
}

// ------------------------------------------------------------------
// Kernel PF: finalize invS[k][i] = 1 / sum_b Spart[b][k][i]
// 1 block, 1024 threads
// ------------------------------------------------------------------
__global__ void kPF_finalize(int nblocks) {
    int u = threadIdx.x;
    float s = 0.0f;
    for (int b = 0; b < nblocks; b++)
        s += g_Spart[b * (KNB * NCH) + u];
    g_invS[u] = 1.0f / s;
}

// ------------------------------------------------------------------
// Kernel PC: out[j] = sum_k sum_i dec_t[id_jk][i] * win * invS[k][i]
// warp-per-j, lane = i. 8 warps/block.
// ------------------------------------------------------------------
__global__ void __launch_bounds__(256) kPC_output(
        const float* __restrict__ nd, const int* __restrict__ nid,
        const int* __restrict__ labels, float* __restrict__ out, int N) {
    __shared__ float a_s[MCL * NCH];
    __shared__ float ivs[KNB * NCH];   // [k][i]
    int t = threadIdx.x;
    for (int u = t; u < MCL * NCH; u += 256) a_s[u] = g_a[u];
    for (int u = t; u < KNB * NCH; u += 256) ivs[u] = g_invS[u];
    __syncthreads();

    int lane = t & 31, wid = t >> 5;
    int j = blockIdx.x * 8 + wid;
    if (j >= N) return;   // uniform per warp

    float dd  = nd[(size_t)j * KNB + lane];
    float d2l = dd * dd;
    int myid  = nid[(size_t)j * KNB + lane];
    int lab   = labels[j];
    float a   = a_s[lab * NCH + lane];

    float acc = 0.0f;
    #pragma unroll
    for (int k = 0; k < KNB; k++) {
        float d2 = __shfl_sync(0xffffffffu, d2l, k);
        int idk  = __shfl_sync(0xffffffffu, myid, k);
        float v  = g_dect[(size_t)idk * NCH + lane];   // coalesced 128B gather
        float win = fmaxf(fmaf(-d2, a, 1.0f), 0.0f);
        acc = fmaf(v * win, ivs[k * NCH + lane], acc);
    }

    #pragma unroll
    for (int o = 16; o > 0; o >>= 1)
        acc += __shfl_xor_sync(0xffffffffu, acc, o);
    if (lane == 0) out[j] = acc;
}

// ------------------------------------------------------------------
extern "C" void kernel_launch(void* const* d_in, const int* in_sizes, int n_in,
                              void* d_out, int out_size) {
    const float* x       = (const float*)d_in[0];
    const float* enc_w   = (const float*)d_in[1];
    const float* enc_b   = (const float*)d_in[2];
    const float* decoder = (const float*)d_in[3];
    const float* bw_w    = (const float*)d_in[4];
    const float* bw_b    = (const float*)d_in[5];
    const float* nd      = (const float*)d_in[6];
    const int*   nid     = (const int*)d_in[7];
    const int*   labels  = (const int*)d_in[8];
    float* out = (float*)d_out;
    int N = in_sizes[0];

    kA_encoded<<<dim3(16, NCH), 256>>>(enc_w, x, N);
    kB_bandwidths<<<1, NCH * MCL>>>(bw_w, bw_b, enc_b);
    kT_transpose<<<(N + 255) / 256, 256>>>(decoder, N);
    kPB_sums<<<PB_BLOCKS, 512>>>(nd, labels, N);
    kPF_finalize<<<1, KNB * NCH>>>(PB_BLOCKS);
    kPC_output<<<(N + 7) / 8, 256>>>(nd, nid, labels, out, N);
}